// round 4
// baseline (speedup 1.0000x reference)
#include <cuda_runtime.h>
#include <cuda_bf16.h>
#include <cstdint>

#define EPSF 1e-8f
static constexpr int B_  = 8;
static constexpr int N_  = 256;
static constexpr int NF_ = 2048;

__device__ __nv_bfloat16 g_K[B_ * N_ * N_];   // bf16 K, L2-resident
__device__ float g_rsK[B_ * N_];              // rowsum(K)
__device__ float g_p  [B_ * N_];
__device__ float g_u  [B_ * N_];
__device__ float g_v  [B_ * N_];
__device__ float g_Kv [B_ * N_];
__device__ float g_KTu[B_ * N_];
__device__ float g_S  [B_];
__device__ int   g_conv[B_];

// ---------------------------------------------------------------------------
// helpers
// ---------------------------------------------------------------------------
__device__ __forceinline__ void unpack8(uint4 kr, float* f)
{
    float2 f0 = __bfloat1622float2(*reinterpret_cast<__nv_bfloat162*>(&kr.x));
    float2 f1 = __bfloat1622float2(*reinterpret_cast<__nv_bfloat162*>(&kr.y));
    float2 f2 = __bfloat1622float2(*reinterpret_cast<__nv_bfloat162*>(&kr.z));
    float2 f3 = __bfloat1622float2(*reinterpret_cast<__nv_bfloat162*>(&kr.w));
    f[0] = f0.x; f[1] = f0.y; f[2] = f1.x; f[3] = f1.y;
    f[4] = f2.x; f[5] = f2.y; f[6] = f3.x; f[7] = f3.y;
}

__device__ __forceinline__ float dot8(uint4 kr, const float* vj)
{
    float kf[8];
    unpack8(kr, kf);
    float acc = 0.f;
#pragma unroll
    for (int x = 0; x < 8; ++x) acc = fmaf(kf[x], vj[x], acc);
    return acc;
}

// 256-thread block reductions
__device__ __forceinline__ float blk_sum256(float val, float* red)
{
#pragma unroll
    for (int o = 16; o; o >>= 1) val += __shfl_xor_sync(0xffffffffu, val, o);
    if ((threadIdx.x & 31) == 0) red[threadIdx.x >> 5] = val;
    __syncthreads();
    if (threadIdx.x < 32) {
        float s = (threadIdx.x < 8) ? red[threadIdx.x] : 0.f;
#pragma unroll
        for (int o = 4; o; o >>= 1) s += __shfl_xor_sync(0xffffffffu, s, o);
        if (threadIdx.x == 0) red[8] = s;
    }
    __syncthreads();
    float r = red[8];
    __syncthreads();
    return r;
}

__device__ __forceinline__ float blk_max256(float val, float* red)
{
#pragma unroll
    for (int o = 16; o; o >>= 1) val = fmaxf(val, __shfl_xor_sync(0xffffffffu, val, o));
    if ((threadIdx.x & 31) == 0) red[threadIdx.x >> 5] = val;
    __syncthreads();
    if (threadIdx.x < 32) {
        float s = (threadIdx.x < 8) ? red[threadIdx.x] : -3.4e38f;
#pragma unroll
        for (int o = 4; o; o >>= 1) s = fmaxf(s, __shfl_xor_sync(0xffffffffu, s, o));
        if (threadIdx.x == 0) red[8] = s;
    }
    __syncthreads();
    float r = red[8];
    __syncthreads();
    return r;
}

// 1024-thread block reduction (fallback kernel only)
__device__ __forceinline__ float blk_sum1024(float val, float* red)
{
#pragma unroll
    for (int o = 16; o; o >>= 1) val += __shfl_xor_sync(0xffffffffu, val, o);
    if ((threadIdx.x & 31) == 0) red[threadIdx.x >> 5] = val;
    __syncthreads();
    if (threadIdx.x < 32) {
        float s = red[threadIdx.x];
#pragma unroll
        for (int o = 16; o; o >>= 1) s += __shfl_xor_sync(0xffffffffu, s, o);
        if (threadIdx.x == 0) red[32] = s;
    }
    __syncthreads();
    float r = red[32];
    __syncthreads();
    return r;
}

// ---------------------------------------------------------------------------
// Kernel 1: block-mean pooling -> row-normalize -> K=(W+EPS)^10 (bf16)
// plus per-row rowsum(K).  Grid (256, 8), 256 threads.  (~24us, DRAM roofline)
// ---------------------------------------------------------------------------
__global__ void __launch_bounds__(256) pool_build_k(const float* __restrict__ A)
{
    const int I = blockIdx.x, b = blockIdx.y;
    const int t = threadIdx.x;
    const float* base = A + ((size_t)b * NF_ + (size_t)I * 8) * NF_;

    float4 a0 = make_float4(0.f, 0.f, 0.f, 0.f);
    float4 a1 = make_float4(0.f, 0.f, 0.f, 0.f);
#pragma unroll
    for (int r = 0; r < 8; ++r) {
        const float4* row = reinterpret_cast<const float4*>(base + (size_t)r * NF_);
        float4 f0 = __ldcs(row + t);
        float4 f1 = __ldcs(row + t + 256);
        a0.x += f0.x; a0.y += f0.y; a0.z += f0.z; a0.w += f0.w;
        a1.x += f1.x; a1.y += f1.y; a1.z += f1.z; a1.w += f1.w;
    }
    float s0 = (a0.x + a0.y) + (a0.z + a0.w);
    float s1 = (a1.x + a1.y) + (a1.z + a1.w);
    s0 += __shfl_xor_sync(0xffffffffu, s0, 1);
    s1 += __shfl_xor_sync(0xffffffffu, s1, 1);

    __shared__ float srow[256];
    __shared__ float red[9];
    if ((t & 1) == 0) {
        srow[(t >> 1)]       = s0 * (1.0f / 64.0f);
        srow[128 + (t >> 1)] = s1 * (1.0f / 64.0f);
    }
    __syncthreads();

    float w = fmaxf(srow[t], 0.0f);
    float rv = w;
#pragma unroll
    for (int o = 16; o; o >>= 1) rv += __shfl_xor_sync(0xffffffffu, rv, o);
    if ((t & 31) == 0) red[t >> 5] = rv;
    __syncthreads();
    if (t == 0) {
        float s = 0.f;
#pragma unroll
        for (int i = 0; i < 8; ++i) s += red[i];
        red[8] = s;
    }
    __syncthreads();
    float rowsum = red[8];
    __syncthreads();                 // protect red[] before reuse

    float W = (rowsum > EPSF) ? (w / (rowsum + EPSF)) : (1.0f / N_);
    float x  = W + EPSF;
    float x2 = x * x, x4 = x2 * x2, x8 = x4 * x4;
    __nv_bfloat16 kb = __float2bfloat16(x8 * x2);           // K = x^10 (bf16)
    g_K[((size_t)b * N_ + I) * N_ + t] = kb;

    // rowsum of the bf16-rounded K (closed-form Kv0 = rsK/256 in kernel 2a)
    float kf = __bfloat162float(kb);
#pragma unroll
    for (int o = 16; o; o >>= 1) kf += __shfl_xor_sync(0xffffffffu, kf, o);
    if ((t & 31) == 0) red[t >> 5] = kf;
    __syncthreads();
    if (t == 0) {
        float s = 0.f;
#pragma unroll
        for (int i = 0; i < 8; ++i) s += red[i];
        g_rsK[b * N_ + I] = s;
    }
}

// ---------------------------------------------------------------------------
// Kernel 2a: init + softmax + closed-form first u-update. Grid 8, 256 thr.
//   Kv0[i] = sum_j K[i,j]/256 = rsK[i]/256  (v0 uniform)
// ---------------------------------------------------------------------------
__global__ void __launch_bounds__(256) k2a_init(const float* __restrict__ gamma_g)
{
    __shared__ float red[10];
    const int b = blockIdx.x, t = threadIdx.x;

    g_KTu[b * N_ + t] = 0.f;
    if (t == 0) { g_S[b] = 0.f; g_conv[b] = 0; }

    float g = gamma_g[b * N_ + t];
    float m = blk_max256(g, red);
    float e = expf(g - m);
    float s = blk_sum256(e, red);
    float p = e / s;
    g_p[b * N_ + t] = p;
    g_u[b * N_ + t] = p / (g_rsK[b * N_ + t] * (1.0f / N_) + EPSF);
}

// ---------------------------------------------------------------------------
// Kernel 2b: partial K^T u1 over 32 rows per CTA. Grid (8 rowgrp, 8 batch).
// ---------------------------------------------------------------------------
__global__ void __launch_bounds__(256) k2b_ktu()
{
    __shared__ float u_s[32];
    __shared__ float part[8][256];
    const int g = blockIdx.x, b = blockIdx.y;
    const int t = threadIdx.x;
    const int rg = t >> 5, lane = t & 31;
    const int jj = lane * 8;

    if (t < 32) u_s[t] = g_u[b * N_ + g * 32 + t];
    __syncthreads();

    float acc[8] = {0, 0, 0, 0, 0, 0, 0, 0};
#pragma unroll
    for (int k = 0; k < 4; ++k) {
        int i = g * 32 + rg * 4 + k;
        uint4 kr = *reinterpret_cast<const uint4*>(g_K + ((size_t)b * N_ + i) * N_ + jj);
        float kf[8];
        unpack8(kr, kf);
        float uu = u_s[rg * 4 + k];
#pragma unroll
        for (int x = 0; x < 8; ++x) acc[x] = fmaf(kf[x], uu, acc[x]);
    }
#pragma unroll
    for (int x = 0; x < 8; ++x) part[rg][jj + x] = acc[x];
    __syncthreads();

    float s = 0.f;
#pragma unroll
    for (int r = 0; r < 8; ++r) s += part[r][t];
    atomicAdd(&g_KTu[b * N_ + t], s);
}

// ---------------------------------------------------------------------------
// Kernel 2d: v1 = q/(KTu+EPS); Kv1 (row split); u2 = p/(Kv1+EPS);
// bitwise convergence check vs u1; S partial. Grid (8 rowgrp, 8 batch).
// ---------------------------------------------------------------------------
__global__ void __launch_bounds__(256) k2d_kv()
{
    __shared__ float v_s[256];
    const int g = blockIdx.x, b = blockIdx.y;
    const int t = threadIdx.x;
    const int w = t >> 5, lane = t & 31;

    {
        float kt = g_KTu[b * N_ + t];
        float vv = (1.0f / N_) / (kt + EPSF);
        v_s[t] = vv;
        if (g == 0) g_v[b * N_ + t] = vv;
    }
    __syncthreads();

    float vj[8];
#pragma unroll
    for (int x = 0; x < 8; ++x) vj[x] = v_s[lane * 8 + x];

    float sacc = 0.f;
#pragma unroll
    for (int k = 0; k < 4; ++k) {
        int i = g * 32 + w * 4 + k;
        uint4 kr = *reinterpret_cast<const uint4*>(g_K + ((size_t)b * N_ + i) * N_ + lane * 8);
        float acc = dot8(kr, vj);
#pragma unroll
        for (int o = 16; o; o >>= 1) acc += __shfl_xor_sync(0xffffffffu, acc, o);
        if (lane == 0) {
            float u1 = g_u[b * N_ + i];
            float u2 = g_p[b * N_ + i] / (acc + EPSF);
            if (u2 != u1) g_conv[b] = 1;           // not converged
            g_u[b * N_ + i]  = u2;
            g_Kv[b * N_ + i] = acc;
            sacc = fmaf(u2, acc, sacc);
        }
    }
    if (lane == 0) atomicAdd(&g_S[b], sacc);
}

// ---------------------------------------------------------------------------
// Kernel 2e: fallback — completes iterations 1..9 if not converged.
// Grid 8, 1024 threads, K staged in smem. Returns immediately when converged.
// ---------------------------------------------------------------------------
static constexpr int FB_SMEM = 131072 + 16384 + 4 * 1024 + 40 * 4;

__global__ void __launch_bounds__(1024, 1) k2e_fallback()
{
    const int b = blockIdx.x;
    if (g_conv[b] == 0) return;          // converged: (u2, v1, Kv1, S) final

    extern __shared__ char sm[];
    __nv_bfloat16* Ks = reinterpret_cast<__nv_bfloat16*>(sm);        // 131072
    float* part = reinterpret_cast<float*>(sm + 131072);             // 16*256
    float* p    = reinterpret_cast<float*>(sm + 131072 + 16384);     // 256
    float* u    = p + 256;
    float* v    = u + 256;
    float* Kv   = v + 256;
    float* red  = Kv + 256;                                          // 34

    const int t = threadIdx.x;
    const int wid = t >> 5, lane = t & 31;

    {
        const uint4* gk = reinterpret_cast<const uint4*>(g_K + (size_t)b * N_ * N_);
        uint4* sk = reinterpret_cast<uint4*>(Ks);
#pragma unroll
        for (int x = 0; x < 8; ++x) sk[t + 1024 * x] = gk[t + 1024 * x];
    }
    if (t < 256) {
        p[t] = g_p[b * N_ + t];
        u[t] = g_u[b * N_ + t];          // u2
        v[t] = g_v[b * N_ + t];          // v1 (will be overwritten by it1's v-update)
    }
    __syncthreads();

    // complete it1's v-update, then iterations 2..9, then final Kv.
    for (int it = 1; it < 10; ++it) {
        if (it > 1) {
            // u-update: Kv = K v ; u = p/(Kv+EPS)
            float vj[8];
#pragma unroll
            for (int x = 0; x < 8; ++x) vj[x] = v[lane * 8 + x];
#pragma unroll
            for (int k = 0; k < 8; ++k) {
                int i = wid * 8 + k;
                uint4 kr = reinterpret_cast<const uint4*>(Ks + i * N_)[lane];
                float acc = dot8(kr, vj);
#pragma unroll
                for (int o = 16; o; o >>= 1) acc += __shfl_xor_sync(0xffffffffu, acc, o);
                if (lane == 0) u[i] = p[i] / (acc + EPSF);
            }
            __syncthreads();
        }
        // v-update: KTu = K^T u ; v = q/(KTu+EPS)
        {
            const int gg = t >> 6;
            const int jj = (t & 63) * 4;
            float4 a4 = make_float4(0.f, 0.f, 0.f, 0.f);
#pragma unroll
            for (int k = 0; k < 16; ++k) {
                int i = gg * 16 + k;
                uint2 kk = *reinterpret_cast<const uint2*>(Ks + i * N_ + jj);
                float2 f0 = __bfloat1622float2(*reinterpret_cast<__nv_bfloat162*>(&kk.x));
                float2 f1 = __bfloat1622float2(*reinterpret_cast<__nv_bfloat162*>(&kk.y));
                float ui = u[i];
                a4.x = fmaf(f0.x, ui, a4.x);
                a4.y = fmaf(f0.y, ui, a4.y);
                a4.z = fmaf(f1.x, ui, a4.z);
                a4.w = fmaf(f1.y, ui, a4.w);
            }
            *reinterpret_cast<float4*>(part + gg * N_ + jj) = a4;
        }
        __syncthreads();
        if (t < 256) {
            float s = 0.f;
#pragma unroll
            for (int g2 = 0; g2 < 16; ++g2) s += part[g2 * N_ + t];
            v[t] = (1.0f / N_) / (s + EPSF);
        }
        __syncthreads();
    }

    // final Kv with final v; S = sum u*Kv
    {
        float vj[8];
#pragma unroll
        for (int x = 0; x < 8; ++x) vj[x] = v[lane * 8 + x];
#pragma unroll
        for (int k = 0; k < 8; ++k) {
            int i = wid * 8 + k;
            uint4 kr = reinterpret_cast<const uint4*>(Ks + i * N_)[lane];
            float acc = dot8(kr, vj);
#pragma unroll
            for (int o = 16; o; o >>= 1) acc += __shfl_xor_sync(0xffffffffu, acc, o);
            if (lane == 0) Kv[i] = acc;
        }
    }
    __syncthreads();
    float sv = (t < 256) ? u[t] * Kv[t] : 0.f;
    float S = blk_sum1024(sv, red);
    if (t < 256) {
        g_u[b * N_ + t] = u[t];
        g_v[b * N_ + t] = v[t];
    }
    if (t == 0) g_S[b] = S;
}

// ---------------------------------------------------------------------------
// Kernel 3: Kuramoto epilogue. Grid (16, 8), 256 threads.
// ---------------------------------------------------------------------------
__global__ void __launch_bounds__(256) kuramoto_kernel(
    const float* __restrict__ theta_g, const float* __restrict__ gamma_g,
    const float* __restrict__ omega_g, const float* __restrict__ alpha_g,
    const float* __restrict__ logk_g,  float* __restrict__ out)
{
    __shared__ float vsh[256];
    __shared__ float tsh[256];

    const int b     = blockIdx.y;
    const int chunk = blockIdx.x;
    const int t     = threadIdx.x;
    const int row   = t >> 4;
    const int sub   = t & 15;
    const int i     = chunk * 16 + row;
    const int gi    = b * N_ + i;
    const int j0    = sub * 16;

    vsh[t] = g_v[b * N_ + t];
    tsh[t] = theta_g[b * N_ + t];
    __syncthreads();

    uint4 k0 = reinterpret_cast<const uint4*>(g_K + (size_t)gi * N_ + j0)[0];
    uint4 k1 = reinterpret_cast<const uint4*>(g_K + (size_t)gi * N_ + j0)[1];
    float kf[16];
    unpack8(k0, kf);
    unpack8(k1, kf + 8);

    const float4* a4 = reinterpret_cast<const float4*>(alpha_g + (size_t)i * N_ + j0);
    float4 al0 = __ldg(a4 + 0);
    float4 al1 = __ldg(a4 + 1);
    float4 al2 = __ldg(a4 + 2);
    float4 al3 = __ldg(a4 + 3);
    float al[16] = {al0.x, al0.y, al0.z, al0.w, al1.x, al1.y, al1.z, al1.w,
                    al2.x, al2.y, al2.z, al2.w, al3.x, al3.y, al3.z, al3.w};

    const float ti = tsh[i];
    float acc = 0.f;
#pragma unroll
    for (int x = 0; x < 16; ++x) {
        float d = tsh[j0 + x] - ti - al[x];
        acc = fmaf(kf[x] * vsh[j0 + x], __sinf(d), acc);
    }
#pragma unroll
    for (int o = 8; o; o >>= 1) acc += __shfl_xor_sync(0xffffffffu, acc, o);

    if (sub == 0) {
        float Sinv = 1.0f / (g_S[b] + EPSF);
        float coup = g_u[gi] * Sinv * acc;            // K_COUP = 1
        float kap  = log1pf(expf(logk_g[i]));         // softplus
        float td   = omega_g[i] + coup + kap * (gamma_g[gi] - ti);
        out[gi] = ti + td;                            // DT = 1
    }
}

// ---------------------------------------------------------------------------
extern "C" void kernel_launch(void* const* d_in, const int* in_sizes, int n_in,
                              void* d_out, int out_size)
{
    const float* theta = (const float*)d_in[0];
    const float* gamma = (const float*)d_in[1];
    const float* A     = (const float*)d_in[2];
    const float* omega = (const float*)d_in[3];
    const float* alpha = (const float*)d_in[4];
    const float* logk  = (const float*)d_in[5];
    float* out = (float*)d_out;

    dim3 g1(256, 8);
    pool_build_k<<<g1, 256>>>(A);

    k2a_init<<<B_, 256>>>(gamma);

    dim3 g64(8, 8);
    k2b_ktu<<<g64, 256>>>();
    k2d_kv <<<g64, 256>>>();

    cudaFuncSetAttribute(k2e_fallback, cudaFuncAttributeMaxDynamicSharedMemorySize, FB_SMEM);
    k2e_fallback<<<B_, 1024, FB_SMEM>>>();

    dim3 g3(16, 8);
    kuramoto_kernel<<<g3, 256>>>(theta, gamma, omega, alpha, logk, out);
}

// round 5
// speedup vs baseline: 1.1375x; 1.1375x over previous
#include <cuda_runtime.h>
#include <cuda_bf16.h>
#include <cstdint>

#define EPSF 1e-8f
static constexpr int B_  = 8;
static constexpr int N_  = 256;
static constexpr int NF_ = 2048;

__device__ __nv_bfloat16 g_K[B_ * N_ * N_];   // bf16 K, L2-resident
__device__ float g_KTu[B_ * N_];              // atomically accumulated K^T u1 (zeroed each replay by final kernel)
__device__ float g_p  [B_ * N_];
__device__ float g_u1 [B_ * N_];
__device__ float g_u2 [B_ * N_];
__device__ float g_Kv1[B_ * N_];
__device__ float g_cp [B_ * N_];              // coupling accumulator per row
__device__ int   g_conv[B_];                  // 0 = converged after iter2 (zero-init, reset each replay)

// ---------------------------------------------------------------------------
// helpers
// ---------------------------------------------------------------------------
__device__ __forceinline__ void unpack8(uint4 kr, float* f)
{
    float2 f0 = __bfloat1622float2(*reinterpret_cast<__nv_bfloat162*>(&kr.x));
    float2 f1 = __bfloat1622float2(*reinterpret_cast<__nv_bfloat162*>(&kr.y));
    float2 f2 = __bfloat1622float2(*reinterpret_cast<__nv_bfloat162*>(&kr.z));
    float2 f3 = __bfloat1622float2(*reinterpret_cast<__nv_bfloat162*>(&kr.w));
    f[0] = f0.x; f[1] = f0.y; f[2] = f1.x; f[3] = f1.y;
    f[4] = f2.x; f[5] = f2.y; f[6] = f3.x; f[7] = f3.y;
}

__device__ __forceinline__ float dot8(uint4 kr, const float* vj)
{
    float kf[8];
    unpack8(kr, kf);
    float acc = 0.f;
#pragma unroll
    for (int x = 0; x < 8; ++x) acc = fmaf(kf[x], vj[x], acc);
    return acc;
}

// broadcast block reductions, 256 threads
__device__ __forceinline__ float blk_sum256(float val, float* red)
{
#pragma unroll
    for (int o = 16; o; o >>= 1) val += __shfl_xor_sync(0xffffffffu, val, o);
    if ((threadIdx.x & 31) == 0) red[threadIdx.x >> 5] = val;
    __syncthreads();
    if (threadIdx.x < 32) {
        float s = (threadIdx.x < 8) ? red[threadIdx.x] : 0.f;
#pragma unroll
        for (int o = 4; o; o >>= 1) s += __shfl_xor_sync(0xffffffffu, s, o);
        if (threadIdx.x == 0) red[8] = s;
    }
    __syncthreads();
    float r = red[8];
    __syncthreads();
    return r;
}

__device__ __forceinline__ float blk_max256(float val, float* red)
{
#pragma unroll
    for (int o = 16; o; o >>= 1) val = fmaxf(val, __shfl_xor_sync(0xffffffffu, val, o));
    if ((threadIdx.x & 31) == 0) red[threadIdx.x >> 5] = val;
    __syncthreads();
    if (threadIdx.x < 32) {
        float s = (threadIdx.x < 8) ? red[threadIdx.x] : -3.4e38f;
#pragma unroll
        for (int o = 4; o; o >>= 1) s = fmaxf(s, __shfl_xor_sync(0xffffffffu, s, o));
        if (threadIdx.x == 0) red[8] = s;
    }
    __syncthreads();
    float r = red[8];
    __syncthreads();
    return r;
}

// 1024-thread block reduction (final kernel)
__device__ __forceinline__ float blk_sum1024(float val, float* red)
{
#pragma unroll
    for (int o = 16; o; o >>= 1) val += __shfl_xor_sync(0xffffffffu, val, o);
    if ((threadIdx.x & 31) == 0) red[threadIdx.x >> 5] = val;
    __syncthreads();
    if (threadIdx.x < 32) {
        float s = red[threadIdx.x];
#pragma unroll
        for (int o = 16; o; o >>= 1) s += __shfl_xor_sync(0xffffffffu, s, o);
        if (threadIdx.x == 0) red[32] = s;
    }
    __syncthreads();
    float r = red[32];
    __syncthreads();
    return r;
}

// ---------------------------------------------------------------------------
// Kernel 1: pooling -> K (bf16) + rsK + softmax(gamma) -> u1[I],
// and K^T u1 accumulated into g_KTu via REDG. Grid (256,8), 256 thr.
// ---------------------------------------------------------------------------
__global__ void __launch_bounds__(256) pool_build_k(
    const float* __restrict__ A, const float* __restrict__ gamma_g)
{
    const int I = blockIdx.x, b = blockIdx.y;
    const int t = threadIdx.x;
    const float* base = A + ((size_t)b * NF_ + (size_t)I * 8) * NF_;

    // issue gamma loads early (L2-resident after first CTA of each batch)
    float gmine = gamma_g[b * N_ + t];
    float gI    = gamma_g[b * N_ + I];

    float4 a0 = make_float4(0.f, 0.f, 0.f, 0.f);
    float4 a1 = make_float4(0.f, 0.f, 0.f, 0.f);
#pragma unroll
    for (int r = 0; r < 8; ++r) {
        const float4* row = reinterpret_cast<const float4*>(base + (size_t)r * NF_);
        float4 f0 = __ldcs(row + t);
        float4 f1 = __ldcs(row + t + 256);
        a0.x += f0.x; a0.y += f0.y; a0.z += f0.z; a0.w += f0.w;
        a1.x += f1.x; a1.y += f1.y; a1.z += f1.z; a1.w += f1.w;
    }
    float s0 = (a0.x + a0.y) + (a0.z + a0.w);
    float s1 = (a1.x + a1.y) + (a1.z + a1.w);
    s0 += __shfl_xor_sync(0xffffffffu, s0, 1);
    s1 += __shfl_xor_sync(0xffffffffu, s1, 1);

    __shared__ float srow[256];
    __shared__ float red[10];
    if ((t & 1) == 0) {
        srow[(t >> 1)]       = s0 * (1.0f / 64.0f);
        srow[128 + (t >> 1)] = s1 * (1.0f / 64.0f);
    }
    __syncthreads();

    float w = fmaxf(srow[t], 0.0f);                 // relu(A_lat)
    float rowsum = blk_sum256(w, red);

    float W = (rowsum > EPSF) ? (w / (rowsum + EPSF)) : (1.0f / N_);
    float x  = W + EPSF;
    float x2 = x * x, x4 = x2 * x2, x8 = x4 * x4;
    __nv_bfloat16 kb = __float2bfloat16(x8 * x2);   // K = x^10 (bf16)
    g_K[((size_t)b * N_ + I) * N_ + t] = kb;

    float kf  = __bfloat162float(kb);
    float rsK = blk_sum256(kf, red);                // rowsum of bf16 K

    // softmax(gamma) -> p[I], u1[I] = p/(rsK/256 + EPS)   (Kv0 = rsK/256)
    float m = blk_max256(gmine, red);
    float s = blk_sum256(expf(gmine - m), red);
    float pI  = expf(gI - m) / s;
    float u1I = pI / (rsK * (1.0f / N_) + EPSF);

    // K^T u1 contribution of row I
    atomicAdd(&g_KTu[b * N_ + t], kf * u1I);

    if (t == 0) {
        g_p [b * N_ + I] = pI;
        g_u1[b * N_ + I] = u1I;
    }
}

// ---------------------------------------------------------------------------
// Kernel 2: the single post-pool K pass. Grid (16,8) = 128 CTAs, 256 thr.
// v1 = q/(KTu+EPS); per row i: Kv1, u2 = p/(Kv1+EPS), conv check,
// coupacc = sum_j K_ij v1_j sin(theta_j - theta_i - alpha_ij).
// ---------------------------------------------------------------------------
__global__ void __launch_bounds__(256) epi_main(
    const float* __restrict__ theta_g, const float* __restrict__ alpha_g)
{
    __shared__ float v1sh[256];
    __shared__ float tsh[256];

    const int b     = blockIdx.y;
    const int chunk = blockIdx.x;
    const int t     = threadIdx.x;
    const int row   = t >> 4;
    const int sub   = t & 15;
    const int i     = chunk * 16 + row;
    const int gi    = b * N_ + i;
    const int j0    = sub * 16;

    float kt = g_KTu[b * N_ + t];
    v1sh[t]  = (1.0f / N_) / (kt + EPSF);
    tsh[t]   = theta_g[b * N_ + t];
    __syncthreads();

    uint4 k0 = reinterpret_cast<const uint4*>(g_K + (size_t)gi * N_ + j0)[0];
    uint4 k1 = reinterpret_cast<const uint4*>(g_K + (size_t)gi * N_ + j0)[1];
    float kf[16];
    unpack8(k0, kf);
    unpack8(k1, kf + 8);

    const float4* a4 = reinterpret_cast<const float4*>(alpha_g + (size_t)i * N_ + j0);
    float4 al0 = __ldg(a4 + 0);
    float4 al1 = __ldg(a4 + 1);
    float4 al2 = __ldg(a4 + 2);
    float4 al3 = __ldg(a4 + 3);
    float al[16] = {al0.x, al0.y, al0.z, al0.w, al1.x, al1.y, al1.z, al1.w,
                    al2.x, al2.y, al2.z, al2.w, al3.x, al3.y, al3.z, al3.w};

    const float ti = tsh[i];
    float kv = 0.f, cp = 0.f;
#pragma unroll
    for (int x = 0; x < 16; ++x) {
        float kvj = kf[x] * v1sh[j0 + x];
        kv += kvj;
        float d = tsh[j0 + x] - ti - al[x];
        cp = fmaf(kvj, __sinf(d), cp);
    }
#pragma unroll
    for (int o = 8; o; o >>= 1) {
        kv += __shfl_xor_sync(0xffffffffu, kv, o);
        cp += __shfl_xor_sync(0xffffffffu, cp, o);
    }

    if (sub == 0) {
        float u1 = g_u1[gi];
        float u2 = g_p[gi] / (kv + EPSF);
        if (u2 != u1) g_conv[b] = 1;        // not converged after iter 2
        g_u2 [gi] = u2;
        g_Kv1[gi] = kv;
        g_cp [gi] = cp;
    }
}

// ---------------------------------------------------------------------------
// Kernel 3: final. Grid 8, 1024 thr.
// Converged: S = sum u2*Kv1; out = theta + omega + u2*Sinv*cp + softplus*(gamma-theta)
// Fallback: faithful 10-iter Sinkhorn from scratch + coupling (K staged in smem).
// Also resets g_KTu / g_conv for the next graph replay.
// ---------------------------------------------------------------------------
static constexpr int FB_SMEM = 131072 + 16384 + 5 * 1024;

__global__ void __launch_bounds__(1024, 1) kfinal(
    const float* __restrict__ theta_g, const float* __restrict__ gamma_g,
    const float* __restrict__ omega_g, const float* __restrict__ alpha_g,
    const float* __restrict__ logk_g,  float* __restrict__ out)
{
    __shared__ float red[34];
    extern __shared__ char sm[];

    const int b = blockIdx.x;
    const int t = threadIdx.x;
    const int conv = g_conv[b];          // uniform per block
    __syncthreads();

    if (conv == 0) {
        // ---------------- converged fast path ----------------
        float u2 = 0.f, kv = 0.f;
        if (t < 256) {
            u2 = g_u2 [b * N_ + t];
            kv = g_Kv1[b * N_ + t];
        }
        float S = blk_sum1024((t < 256) ? u2 * kv : 0.f, red);
        if (t < 256) {
            float Sinv = 1.0f / (S + EPSF);
            float ti   = theta_g[b * N_ + t];
            float coup = u2 * Sinv * g_cp[b * N_ + t];        // K_COUP=1
            float kap  = log1pf(expf(logk_g[t]));             // softplus
            float td   = omega_g[t] + coup + kap * (gamma_g[b * N_ + t] - ti);
            out[b * N_ + t] = ti + td;                        // DT=1
        }
    } else {
        // ---------------- fallback: faithful full solve ----------------
        __nv_bfloat16* Ks = reinterpret_cast<__nv_bfloat16*>(sm);        // 131072
        float* part = reinterpret_cast<float*>(sm + 131072);             // 16*256
        float* p    = reinterpret_cast<float*>(sm + 131072 + 16384);     // 256
        float* u    = p + 256;
        float* v    = u + 256;
        float* Kv   = v + 256;
        float* th   = Kv + 256;

        const int wid = t >> 5, lane = t & 31;

        {
            const uint4* gk = reinterpret_cast<const uint4*>(g_K + (size_t)b * N_ * N_);
            uint4* sk = reinterpret_cast<uint4*>(Ks);
#pragma unroll
            for (int x = 0; x < 8; ++x) sk[t + 1024 * x] = gk[t + 1024 * x];
        }
        if (t < 256) {
            p[t]  = g_p[b * N_ + t];
            u[t]  = 1.0f / N_;
            v[t]  = 1.0f / N_;
            th[t] = theta_g[b * N_ + t];
        }
        __syncthreads();

        for (int it = 0; it < 10; ++it) {
            // u-update
            {
                float vj[8];
#pragma unroll
                for (int x = 0; x < 8; ++x) vj[x] = v[lane * 8 + x];
#pragma unroll
                for (int k = 0; k < 8; ++k) {
                    int i = wid * 8 + k;
                    uint4 kr = reinterpret_cast<const uint4*>(Ks + i * N_)[lane];
                    float acc = dot8(kr, vj);
#pragma unroll
                    for (int o = 16; o; o >>= 1) acc += __shfl_xor_sync(0xffffffffu, acc, o);
                    if (lane == 0) u[i] = p[i] / (acc + EPSF);
                }
                __syncthreads();
            }
            // v-update
            {
                const int gg = t >> 6;
                const int jj = (t & 63) * 4;
                float4 a4 = make_float4(0.f, 0.f, 0.f, 0.f);
#pragma unroll
                for (int k = 0; k < 16; ++k) {
                    int i = gg * 16 + k;
                    uint2 kk = *reinterpret_cast<const uint2*>(Ks + i * N_ + jj);
                    float2 f0 = __bfloat1622float2(*reinterpret_cast<__nv_bfloat162*>(&kk.x));
                    float2 f1 = __bfloat1622float2(*reinterpret_cast<__nv_bfloat162*>(&kk.y));
                    float ui = u[i];
                    a4.x = fmaf(f0.x, ui, a4.x);
                    a4.y = fmaf(f0.y, ui, a4.y);
                    a4.z = fmaf(f1.x, ui, a4.z);
                    a4.w = fmaf(f1.y, ui, a4.w);
                }
                *reinterpret_cast<float4*>(part + gg * N_ + jj) = a4;
            }
            __syncthreads();
            if (t < 256) {
                float s = 0.f;
#pragma unroll
                for (int g2 = 0; g2 < 16; ++g2) s += part[g2 * N_ + t];
                v[t] = (1.0f / N_) / (s + EPSF);
            }
            __syncthreads();
        }

        // final Kv with final v
        {
            float vj[8];
#pragma unroll
            for (int x = 0; x < 8; ++x) vj[x] = v[lane * 8 + x];
#pragma unroll
            for (int k = 0; k < 8; ++k) {
                int i = wid * 8 + k;
                uint4 kr = reinterpret_cast<const uint4*>(Ks + i * N_)[lane];
                float acc = dot8(kr, vj);
#pragma unroll
                for (int o = 16; o; o >>= 1) acc += __shfl_xor_sync(0xffffffffu, acc, o);
                if (lane == 0) Kv[i] = acc;
            }
        }
        __syncthreads();
        float S = blk_sum1024((t < 256) ? u[t] * Kv[t] : 0.f, red);
        float Sinv = 1.0f / (S + EPSF);

        // coupling + output (R1-style)
        {
            float vj[8], tj[8];
#pragma unroll
            for (int x = 0; x < 8; ++x) {
                vj[x] = v[lane * 8 + x];
                tj[x] = th[lane * 8 + x];
            }
            const float4* a4p = reinterpret_cast<const float4*>(alpha_g);
#pragma unroll
            for (int k = 0; k < 8; ++k) {
                int i = wid * 8 + k;
                float ti = th[i];
                uint4 kr = reinterpret_cast<const uint4*>(Ks + i * N_)[lane];
                float kf[8];
                unpack8(kr, kf);
                float4 al0 = __ldg(a4p + i * 64 + lane * 2);
                float4 al1 = __ldg(a4p + i * 64 + lane * 2 + 1);
                float al[8] = {al0.x, al0.y, al0.z, al0.w, al1.x, al1.y, al1.z, al1.w};
                float acc = 0.f;
#pragma unroll
                for (int x = 0; x < 8; ++x) {
                    float d = tj[x] - ti - al[x];
                    acc = fmaf(kf[x] * vj[x], __sinf(d), acc);
                }
#pragma unroll
                for (int o = 16; o; o >>= 1) acc += __shfl_xor_sync(0xffffffffu, acc, o);
                if (lane == 0) {
                    float coup = u[i] * Sinv * acc;
                    float kap  = log1pf(expf(logk_g[i]));
                    float td   = omega_g[i] + coup + kap * (gamma_g[b * N_ + i] - ti);
                    out[b * N_ + i] = ti + td;
                }
            }
        }
    }

    // -------- housekeeping for next graph replay --------
    __syncthreads();
    if (t < 256) g_KTu[b * N_ + t] = 0.f;
    if (t == 0)  g_conv[b] = 0;
}

// ---------------------------------------------------------------------------
extern "C" void kernel_launch(void* const* d_in, const int* in_sizes, int n_in,
                              void* d_out, int out_size)
{
    const float* theta = (const float*)d_in[0];
    const float* gamma = (const float*)d_in[1];
    const float* A     = (const float*)d_in[2];
    const float* omega = (const float*)d_in[3];
    const float* alpha = (const float*)d_in[4];
    const float* logk  = (const float*)d_in[5];
    float* out = (float*)d_out;

    dim3 g1(256, 8);
    pool_build_k<<<g1, 256>>>(A, gamma);

    dim3 g2(16, 8);
    epi_main<<<g2, 256>>>(theta, alpha);

    cudaFuncSetAttribute(kfinal, cudaFuncAttributeMaxDynamicSharedMemorySize, FB_SMEM);
    kfinal<<<B_, 1024, FB_SMEM>>>(theta, gamma, omega, alpha, logk, out);
}